// round 1
// baseline (speedup 1.0000x reference)
#include <cuda_runtime.h>
#include <math.h>
#include <float.h>

#define NN 50000
#define EE 300000
#define BB 256
#define FF 128
#define F2C 256
#define AA 2016
#define LL 10
#define NEGS 0.01f
#define EPSV 1e-5f

// ---------------- scratch (static device globals; no allocation allowed) ----
__device__ float g_hA[NN * F2C];
__device__ float g_hB[NN * F2C];
__device__ float g_agg[NN * F2C];
__device__ float g_invdeg[NN];
__device__ int   g_deg[NN];
__device__ int   g_off[NN + 1];
__device__ int   g_cur[NN];
__device__ int   g_srcs[EE];
__device__ int   g_gcnt[BB];
__device__ int   g_gstart[BB];
__device__ float g_g[BB * F2C];
__device__ float g_y1[BB * F2C];
__device__ float g_y2[BB * FF];

// ---------------- setup kernels --------------------------------------------
__global__ void k_zero() {
    int i = blockIdx.x * blockDim.x + threadIdx.x;
    if (i < NN) g_deg[i] = 0;
    if (i < BB) g_gcnt[i] = 0;
}

__global__ void k_embed(const int* __restrict__ x, const float* __restrict__ emb) {
    int idx = blockIdx.x * blockDim.x + threadIdx.x;
    if (idx >= NN * F2C) return;
    int node = idx >> 8;
    int c = idx & 255;
    int tok = x[node * 2 + (c >> 7)];
    g_hA[idx] = emb[tok * FF + (c & 127)];   // emb row 0 is zero already
}

__global__ void k_deg(const int* __restrict__ ei) {
    int e = blockIdx.x * blockDim.x + threadIdx.x;
    if (e < EE) atomicAdd(&g_deg[ei[EE + e]], 1);
}

__global__ void k_scan() {
    __shared__ int sh[1024];
    int tid = threadIdx.x;
    const int per = (NN + 1023) / 1024;
    int beg = tid * per; if (beg > NN) beg = NN;
    int end = beg + per; if (end > NN) end = NN;
    int s = 0;
    for (int i = beg; i < end; i++) s += g_deg[i];
    sh[tid] = s;
    __syncthreads();
    for (int ofs = 1; ofs < 1024; ofs <<= 1) {
        int add = (tid >= ofs) ? sh[tid - ofs] : 0;
        __syncthreads();
        sh[tid] += add;
        __syncthreads();
    }
    int run = (tid > 0) ? sh[tid - 1] : 0;
    for (int i = beg; i < end; i++) { g_off[i] = run; run += g_deg[i]; }
    if (tid == 1023) g_off[NN] = sh[1023];
}

__global__ void k_prep() {
    int i = blockIdx.x * blockDim.x + threadIdx.x;
    if (i >= NN) return;
    g_cur[i] = g_off[i];
    int d = g_deg[i];
    g_invdeg[i] = 1.0f / (float)(d > 0 ? d : 1);
}

__global__ void k_scatter(const int* __restrict__ ei) {
    int e = blockIdx.x * blockDim.x + threadIdx.x;
    if (e >= EE) return;
    int d = ei[EE + e];
    int pos = atomicAdd(&g_cur[d], 1);
    g_srcs[pos] = ei[e];
}

// deterministic aggregation order: sort each node's neighbor list
__global__ void k_sortseg() {
    int n = blockIdx.x * blockDim.x + threadIdx.x;
    if (n >= NN) return;
    int beg = g_off[n], end = g_off[n + 1];
    for (int i = beg + 1; i < end; i++) {
        int v = g_srcs[i];
        int j = i - 1;
        while (j >= beg && g_srcs[j] > v) { g_srcs[j + 1] = g_srcs[j]; j--; }
        g_srcs[j + 1] = v;
    }
}

__global__ void k_gcnt(const int* __restrict__ batch) {
    int i = blockIdx.x * blockDim.x + threadIdx.x;
    if (i < NN) atomicAdd(&g_gcnt[batch[i]], 1);
}

__global__ void k_gscan() {
    __shared__ int sh[BB];
    int tid = threadIdx.x;
    sh[tid] = g_gcnt[tid];
    __syncthreads();
    for (int ofs = 1; ofs < BB; ofs <<= 1) {
        int add = (tid >= ofs) ? sh[tid - ofs] : 0;
        __syncthreads();
        sh[tid] += add;
        __syncthreads();
    }
    g_gstart[tid] = sh[tid] - g_gcnt[tid];
}

// ---------------- per-layer kernels -----------------------------------------
// mean-aggregate neighbors: one block per node, one thread per channel
__global__ void k_aggregate(int in_sel) {
    const float* __restrict__ h = in_sel ? g_hB : g_hA;
    int n = blockIdx.x;
    int c = threadIdx.x;
    int beg = g_off[n], end = g_off[n + 1];
    float s = 0.0f;
    for (int i = beg; i < end; i++) {
        int sn = g_srcs[i];
        s += h[sn * F2C + c];
    }
    g_agg[n * F2C + c] = s * g_invdeg[n];
}

// fused SAGE GEMM: hout = act(agg@Wl + bl + hin@Wr), act(v)=leaky(v)+v
#define BM 128
#define BN 64
#define BK 16
#define TM 8
#define TN 4
__global__ __launch_bounds__(256) void k_gemm(int in_sel,
                                              const float* __restrict__ Wl,
                                              const float* __restrict__ Wr,
                                              const float* __restrict__ bl) {
    __shared__ float As[BK][BM];
    __shared__ float Bs[BK][BN];
    const float* __restrict__ hin = in_sel ? g_hB : g_hA;
    float* __restrict__ hout = in_sel ? g_hA : g_hB;

    int bm = blockIdx.x * BM;
    int bn = blockIdx.y * BN;
    int tid = threadIdx.x;
    int ty = tid >> 4;        // 0..15
    int tx = tid & 15;        // 0..15

    float acc[TM][TN];
#pragma unroll
    for (int i = 0; i < TM; i++)
#pragma unroll
        for (int j = 0; j < TN; j++) acc[i][j] = 0.0f;

    for (int phase = 0; phase < 2; phase++) {
        const float* A = phase ? hin : g_agg;
        const float* W = phase ? Wr : Wl;
        for (int kt = 0; kt < F2C; kt += BK) {
            // A tile: [BM x BK] -> transposed smem As[BK][BM]
#pragma unroll
            for (int l = 0; l < 2; l++) {
                int i = tid + l * 256;        // float4 index 0..511
                int row = i >> 2;             // 0..127
                int c4 = i & 3;               // 0..3
                int gr = bm + row;
                float4 v = (gr < NN) ? *(const float4*)(A + gr * F2C + kt + c4 * 4)
                                     : make_float4(0.f, 0.f, 0.f, 0.f);
                As[c4 * 4 + 0][row] = v.x;
                As[c4 * 4 + 1][row] = v.y;
                As[c4 * 4 + 2][row] = v.z;
                As[c4 * 4 + 3][row] = v.w;
            }
            // B tile: [BK x BN]
            {
                int kr = tid >> 4;   // 0..15
                int c4 = tid & 15;   // 0..15
                *(float4*)&Bs[kr][c4 * 4] = *(const float4*)(W + (kt + kr) * F2C + bn + c4 * 4);
            }
            __syncthreads();
#pragma unroll
            for (int k = 0; k < BK; k++) {
                float a[TM], b[TN];
                *(float4*)&a[0] = *(float4*)&As[k][ty * TM];
                *(float4*)&a[4] = *(float4*)&As[k][ty * TM + 4];
                *(float4*)&b[0] = *(float4*)&Bs[k][tx * TN];
#pragma unroll
                for (int i = 0; i < TM; i++)
#pragma unroll
                    for (int j = 0; j < TN; j++) acc[i][j] += a[i] * b[j];
            }
            __syncthreads();
        }
    }

    int gc = bn + tx * TN;
    float bb[TN];
    *(float4*)bb = *(const float4*)(bl + gc);
#pragma unroll
    for (int i = 0; i < TM; i++) {
        int gr = bm + ty * TM + i;
        if (gr < NN) {
            float r[TN];
#pragma unroll
            for (int j = 0; j < TN; j++) {
                float c = acc[i][j] + bb[j];
                r[j] = (c > 0.0f) ? 2.0f * c : (1.0f + NEGS) * c;   // leaky(c)+c
            }
            *(float4*)(hout + gr * F2C + gc) = *(float4*)r;
        }
    }
}

// ---------------- GraphNorm + SoftmaxAggregation (block per graph) ---------
__global__ void k_gn_softmax(const float* __restrict__ gw, const float* __restrict__ gb,
                             const float* __restrict__ gs, const float* __restrict__ tptr) {
    float* __restrict__ h = g_hA;   // LL=10 is even -> final h lives in g_hA
    int b = blockIdx.x;
    int c = threadIdx.x;
    int start = g_gstart[b], cnt = g_gcnt[b];
    float cntf = (cnt > 0) ? (float)cnt : 1.0f;
    float t = tptr[0];

    float s = 0.0f;
    for (int i = 0; i < cnt; i++) s += h[(start + i) * F2C + c];
    float ms = (s / cntf) * gs[c];

    float v = 0.0f;
    for (int i = 0; i < cnt; i++) {
        float o = h[(start + i) * F2C + c] - ms;
        v += o * o;
    }
    float inv = 1.0f / sqrtf(v / cntf + EPSV);
    float w = gw[c], bias = gb[c];
    for (int i = 0; i < cnt; i++) {
        int idx = (start + i) * F2C + c;
        h[idx] = w * (h[idx] - ms) * inv + bias;
    }

    float m = -FLT_MAX;
    for (int i = 0; i < cnt; i++) m = fmaxf(m, h[(start + i) * F2C + c] * t);
    float se = 0.0f, sh = 0.0f;
    for (int i = 0; i < cnt; i++) {
        float hv = h[(start + i) * F2C + c];
        float e = expf(hv * t - m);
        se += e;
        sh += e * hv;
    }
    g_g[b * F2C + c] = (cnt > 0) ? (sh / se) : 0.0f;
}

// ---------------- MLP head ---------------------------------------------------
__global__ void k_mlp1(const float* __restrict__ W, const float* __restrict__ bias) {
    __shared__ float row[F2C];
    int b = blockIdx.x, j = threadIdx.x;
    row[j] = g_g[b * F2C + j];
    __syncthreads();
    float s = bias[j];
#pragma unroll 8
    for (int k = 0; k < F2C; k++) s += row[k] * W[k * F2C + j];
    g_y1[b * F2C + j] = (s > 0.0f) ? s : NEGS * s;
}

__global__ void k_mlp2(const float* __restrict__ W, const float* __restrict__ bias) {
    __shared__ float row[F2C];
    int b = blockIdx.x, j = threadIdx.x;
    row[j] = g_y1[b * F2C + j];
    row[j + 128] = g_y1[b * F2C + j + 128];
    __syncthreads();
    float s = bias[j];
#pragma unroll 8
    for (int k = 0; k < F2C; k++) s += row[k] * W[k * FF + j];
    g_y2[b * FF + j] = (s > 0.0f) ? s : NEGS * s;
}

__global__ void k_mlp3(const float* __restrict__ W, const float* __restrict__ bias,
                       float* __restrict__ out) {
    __shared__ float row[FF];
    int b = blockIdx.x, j = threadIdx.x;
    if (j < FF) row[j] = g_y2[b * FF + j];
    __syncthreads();
    float acc[8];
#pragma unroll
    for (int r = 0; r < 8; r++) {
        int idx = j + 256 * r;
        acc[r] = (idx < AA) ? bias[idx] : 0.0f;
    }
    for (int k = 0; k < FF; k++) {
        float rv = row[k];
        const float* wr = W + k * AA;
#pragma unroll
        for (int r = 0; r < 8; r++) {
            int idx = j + 256 * r;
            if (idx < AA) acc[r] += rv * wr[idx];
        }
    }
#pragma unroll
    for (int r = 0; r < 8; r++) {
        int idx = j + 256 * r;
        if (idx < AA) out[b * AA + idx] = acc[r];
    }
}

// ---------------- launch ------------------------------------------------------
extern "C" void kernel_launch(void* const* d_in, const int* in_sizes, int n_in,
                              void* d_out, int out_size) {
    const int*   x     = (const int*)d_in[0];
    const int*   ei    = (const int*)d_in[1];
    const int*   batch = (const int*)d_in[2];
    const float* emb   = (const float*)d_in[3];
    const float* Wl    = (const float*)d_in[4];
    const float* bl    = (const float*)d_in[5];
    const float* Wr    = (const float*)d_in[6];
    const float* gw    = (const float*)d_in[7];
    const float* gb    = (const float*)d_in[8];
    const float* gs    = (const float*)d_in[9];
    const float* t     = (const float*)d_in[10];
    const float* W1    = (const float*)d_in[11];
    const float* b1    = (const float*)d_in[12];
    const float* W2    = (const float*)d_in[13];
    const float* b2    = (const float*)d_in[14];
    const float* W3    = (const float*)d_in[15];
    const float* b3    = (const float*)d_in[16];
    float* out = (float*)d_out;

    // graph structure (recomputed each call; deterministic)
    k_zero<<<(NN + 255) / 256, 256>>>();
    k_embed<<<(NN * F2C + 255) / 256, 256>>>(x, emb);
    k_deg<<<(EE + 255) / 256, 256>>>(ei);
    k_scan<<<1, 1024>>>();
    k_prep<<<(NN + 255) / 256, 256>>>();
    k_scatter<<<(EE + 255) / 256, 256>>>(ei);
    k_sortseg<<<(NN + 255) / 256, 256>>>();
    k_gcnt<<<(NN + 255) / 256, 256>>>(batch);
    k_gscan<<<1, BB>>>();

    // 10 SAGE layers; ping-pong hA <-> hB (even count -> ends in g_hA)
    dim3 ggrid((NN + BM - 1) / BM, F2C / BN);
    for (int i = 0; i < LL; i++) {
        int in_sel = i & 1;   // 0: read hA, write hB; 1: read hB, write hA
        k_aggregate<<<NN, F2C>>>(in_sel);
        k_gemm<<<ggrid, 256>>>(in_sel, Wl + i * F2C * F2C, Wr + i * F2C * F2C, bl + i * F2C);
    }

    // GraphNorm + softmax aggregation -> g_g [B, F2]
    k_gn_softmax<<<BB, F2C>>>(gw, gb, gs, t);

    // MLP head -> out [B, A]
    k_mlp1<<<BB, F2C>>>(W1, b1);
    k_mlp2<<<BB, FF>>>(W2, b2);
    k_mlp3<<<BB, 256>>>(W3, b3, out);
}

// round 4
// speedup vs baseline: 1.4777x; 1.4777x over previous
#include <cuda_runtime.h>
#include <cuda_bf16.h>
#include <mma.h>
#include <math.h>
#include <float.h>
#include <stdint.h>

using namespace nvcuda;

#define NN 50000
#define EE 300000
#define BB 256
#define FF 128
#define F2C 256
#define AA 2016
#define LL 10
#define NEGS 0.01f
#define EPSV 1e-5f

#define SCANB ((NN + 256) / 256)
#define KPP 1536              /* K'' */
#define NSLAB 48              /* K'' / 32 */
#define MT 128                /* CTA M tile */
#define GX ((NN + MT - 1) / MT)   /* 391 */

/* dyn smem: staging A0|A1|B0|B1 (4 x 12288B) overlapped with epilogue C (128x132 f32) */
#define STAGE 12288
#define SMEMB 69632

/* ---------------- scratch ---------------- */
__device__ float g_h[NN * F2C];
__device__ __nv_bfloat16 g_agg[(size_t)NN * 512];          /* [agg_hi(256)|agg_lo(256)] */
__device__ __nv_bfloat16 g_hinA[(size_t)NN * 512];         /* [hin_hi(256)|hin_lo(256)] */
__device__ __nv_bfloat16 g_hinB[(size_t)NN * 512];
__device__ __nv_bfloat16 g_Bpack[(size_t)LL * 256 * KPP];  /* per layer: [n][k''] (B^T row-major) */
__device__ float g_invdeg[NN];
__device__ int   g_deg[NN];
__device__ int   g_off[NN + 1];
__device__ int   g_cur[NN];
__device__ int   g_srcs[EE];
__device__ int   g_gcnt[BB];
__device__ int   g_gstart[BB];
__device__ int   g_bsum[SCANB];
__device__ float g_g[BB * F2C];
__device__ float g_y1[BB * F2C];
__device__ float g_y2[BB * FF];

/* ---------------- helpers ---------------- */
__device__ __forceinline__ uint32_t smem_u32(const void* p) {
    uint32_t a;
    asm("{ .reg .u64 t; cvta.to.shared.u64 t, %1; cvt.u32.u64 %0, t; }" : "=r"(a) : "l"(p));
    return a;
}
__device__ __forceinline__ void cp16(uint32_t dst, const void* src, int zf) {
    asm volatile("cp.async.cg.shared.global [%0], [%1], 16, %2;"
                 :: "r"(dst), "l"(src), "r"(zf) : "memory");
}
#define CP_COMMIT() asm volatile("cp.async.commit_group;" ::: "memory")
#define CP_WAIT(n)  asm volatile("cp.async.wait_group %0;" :: "n"(n) : "memory")

/* ---------------- setup kernels ---------------- */
__global__ void k_zero() {
    int i = blockIdx.x * blockDim.x + threadIdx.x;
    if (i < NN) g_deg[i] = 0;
    if (i < BB) g_gcnt[i] = 0;
}

__global__ void k_embed(const int* __restrict__ x, const float* __restrict__ emb) {
    int idx = blockIdx.x * blockDim.x + threadIdx.x;
    if (idx >= NN * F2C) return;
    int node = idx >> 8;
    int c = idx & 255;
    int tok = x[node * 2 + (c >> 7)];
    float v = emb[tok * FF + (c & 127)];
    g_h[idx] = v;
    __nv_bfloat16 hi = __float2bfloat16(v);
    float lo = v - __bfloat162float(hi);
    g_hinA[(size_t)node * 512 + c] = hi;
    g_hinA[(size_t)node * 512 + 256 + c] = __float2bfloat16(lo);
}

__global__ void k_deg(const int* __restrict__ ei) {
    int e = blockIdx.x * blockDim.x + threadIdx.x;
    if (e < EE) atomicAdd(&g_deg[ei[EE + e]], 1);
}

__global__ void k_scan_a() {
    __shared__ int sh[256];
    int b = blockIdx.x, t = threadIdx.x;
    int i = b * 256 + t;
    int v = (i < NN) ? g_deg[i] : 0;
    sh[t] = v;
    __syncthreads();
    for (int o = 1; o < 256; o <<= 1) {
        int add = (t >= o) ? sh[t - o] : 0;
        __syncthreads();
        sh[t] += add;
        __syncthreads();
    }
    if (i <= NN) g_off[i] = sh[t] - v;
    if (t == 255) g_bsum[b] = sh[255];
}
__global__ void k_scan_b() {
    __shared__ int sh[256];
    int t = threadIdx.x;
    int v = (t < SCANB) ? g_bsum[t] : 0;
    sh[t] = v;
    __syncthreads();
    for (int o = 1; o < 256; o <<= 1) {
        int add = (t >= o) ? sh[t - o] : 0;
        __syncthreads();
        sh[t] += add;
        __syncthreads();
    }
    if (t < SCANB) g_bsum[t] = sh[t] - v;
}
__global__ void k_scan_c() {
    int i = blockIdx.x * blockDim.x + threadIdx.x;
    if (i <= NN) g_off[i] += g_bsum[i >> 8];
}

__global__ void k_prep() {
    int i = blockIdx.x * blockDim.x + threadIdx.x;
    if (i >= NN) return;
    g_cur[i] = g_off[i];
    int d = g_deg[i];
    g_invdeg[i] = 1.0f / (float)(d > 0 ? d : 1);
}

__global__ void k_scatter(const int* __restrict__ ei) {
    int e = blockIdx.x * blockDim.x + threadIdx.x;
    if (e >= EE) return;
    int d = ei[EE + e];
    int pos = atomicAdd(&g_cur[d], 1);
    g_srcs[pos] = ei[e];
}

__global__ void k_sortseg() {
    int n = blockIdx.x * blockDim.x + threadIdx.x;
    if (n >= NN) return;
    int beg = g_off[n], end = g_off[n + 1];
    for (int i = beg + 1; i < end; i++) {
        int v = g_srcs[i];
        int j = i - 1;
        while (j >= beg && g_srcs[j] > v) { g_srcs[j + 1] = g_srcs[j]; j--; }
        g_srcs[j + 1] = v;
    }
}

__global__ void k_gcnt(const int* __restrict__ batch) {
    int i = blockIdx.x * blockDim.x + threadIdx.x;
    if (i < NN) atomicAdd(&g_gcnt[batch[i]], 1);
}

__global__ void k_gscan() {
    __shared__ int sh[BB];
    int tid = threadIdx.x;
    sh[tid] = g_gcnt[tid];
    __syncthreads();
    for (int ofs = 1; ofs < BB; ofs <<= 1) {
        int add = (tid >= ofs) ? sh[tid - ofs] : 0;
        __syncthreads();
        sh[tid] += add;
        __syncthreads();
    }
    g_gstart[tid] = sh[tid] - g_gcnt[tid];
}

/* B pack: row n holds k''∈[0,1536): [0,512)=W_hi(k), [512,1024)=W_hi(k-512), [1024,1536)=W_lo(k-1024)
   where W(k) = k<256 ? Wl[k][n] : Wr[k-256][n] */
__global__ void k_bpack(const float* __restrict__ Wl, const float* __restrict__ Wr) {
    int idx = blockIdx.x * blockDim.x + threadIdx.x;   /* l*512*256 + k*256 + n */
    if (idx >= LL * 512 * 256) return;
    int n = idx & 255;
    int k = (idx >> 8) & 511;
    int l = idx >> 17;
    float w = (k < 256) ? Wl[((size_t)l * 256 + k) * 256 + n]
                        : Wr[((size_t)l * 256 + (k - 256)) * 256 + n];
    __nv_bfloat16 hi = __float2bfloat16(w);
    __nv_bfloat16 lo = __float2bfloat16(w - __bfloat162float(hi));
    __nv_bfloat16* out = g_Bpack + (size_t)l * 256 * KPP + (size_t)n * KPP;
    out[k] = hi;
    out[512 + k] = hi;
    out[1024 + k] = lo;
}

/* mean-aggregate neighbors -> hi/lo bf16 into g_agg */
__global__ void k_aggregate() {
    int n = blockIdx.x;
    int c = threadIdx.x;
    int beg = g_off[n], end = g_off[n + 1];
    float s = 0.0f;
    for (int i = beg; i < end; i++) s += g_h[(size_t)g_srcs[i] * F2C + c];
    float a = s * g_invdeg[n];
    __nv_bfloat16 hi = __float2bfloat16(a);
    float lo = a - __bfloat162float(hi);
    g_agg[(size_t)n * 512 + c] = hi;
    g_agg[(size_t)n * 512 + 256 + c] = __float2bfloat16(lo);
}

/* ---------------- wmma SAGE GEMM ----------------
   C[MT=128, 128] = A''[128, 1536] @ B''[1536, 128(bn half)], bf16 x bf16 -> fp32.
   A'' k'' segments (256 each): agg_hi, hin_hi, agg_lo, hin_lo, agg_hi, hin_hi.
   8 warps: warp w -> (wm = w>>1 in 0..3: 32 rows), (wn = w&1: 64 cols). */
__global__ __launch_bounds__(256, 2)
void k_sage_wmma(int layer, const float* __restrict__ bl,
                 const __nv_bfloat16* __restrict__ hin_in,
                 __nv_bfloat16* __restrict__ hin_out) {
    extern __shared__ char smem[];
    __shared__ float sbias[128];
    const int tid = threadIdx.x;
    const int bm = blockIdx.x * MT;
    const int bn = blockIdx.y;             /* 0 or 1: N half */
    const __nv_bfloat16* __restrict__ Bp = g_Bpack + (size_t)layer * 256 * KPP;
    uint32_t sb = smem_u32(smem);

    if (tid < 128) sbias[tid] = bl[bn * 128 + tid];

    const int r = tid >> 2;          /* 0..63 x2 -> row */
    const int ch = tid & 3;          /* 16B chunk (8 bf16) */

    /* stage bases: A0, A1, B0, B1 */
    auto load_slab = [&](int s, int buf) {
        int kb = s * 32;
        int seg = kb >> 8;                       /* 0..5 */
        int within = kb & 255;
        const __nv_bfloat16* Asrc = (seg & 1) ? hin_in : g_agg;
        int aoff = (((seg >> 1) == 1) ? 256 : 0) + within;   /* seg 2,3 -> lo half */
        uint32_t abase = sb + buf * STAGE;
        uint32_t bbase = sb + 2 * STAGE + buf * STAGE;
#pragma unroll
        for (int l = 0; l < 2; l++) {
            int row = r + l * 64;
            int gr = bm + row;
            int ok = (gr < NN);
            int grc = ok ? gr : (NN - 1);
            cp16(abase + row * 96 + ch * 16,
                 Asrc + (size_t)grc * 512 + aoff + ch * 8, ok ? 16 : 0);
            cp16(bbase + row * 96 + ch * 16,
                 Bp + (size_t)(bn * 128 + row) * KPP + kb + ch * 8, 16);
        }
        CP_COMMIT();
    };

    const int wid = tid >> 5;
    const int wm = wid >> 1;         /* 0..3 */
    const int wn = wid & 1;          /* 0..1 */

    wmma::fragment<wmma::accumulator, 16, 16, 16, float> c[2][4];
#pragma unroll
    for (int i = 0; i < 2; i++)
#pragma unroll
        for (int j = 0; j < 4; j++) wmma::fill_fragment(c[i][j], 0.0f);

    load_slab(0, 0);

    for (int s = 0; s < NSLAB; s++) {
        int buf = s & 1;
        if (s + 1 < NSLAB) {
            load_slab(s + 1, buf ^ 1);
            CP_WAIT(1);
        } else {
            CP_WAIT(0);
        }
        __syncthreads();
        const __nv_bfloat16* As = (const __nv_bfloat16*)(smem + buf * STAGE);
        const __nv_bfloat16* Bs = (const __nv_bfloat16*)(smem + 2 * STAGE + buf * STAGE);
#pragma unroll
        for (int ks = 0; ks < 2; ks++) {
            wmma::fragment<wmma::matrix_a, 16, 16, 16, __nv_bfloat16, wmma::row_major> a[2];
            wmma::fragment<wmma::matrix_b, 16, 16, 16, __nv_bfloat16, wmma::col_major> b[4];
#pragma unroll
            for (int i = 0; i < 2; i++)
                wmma::load_matrix_sync(a[i], As + (wm * 32 + i * 16) * 48 + ks * 16, 48);
#pragma unroll
            for (int j = 0; j < 4; j++)
                wmma::load_matrix_sync(b[j], Bs + (wn * 64 + j * 16) * 48 + ks * 16, 48);
#pragma unroll
            for (int i = 0; i < 2; i++)
#pragma unroll
                for (int j = 0; j < 4; j++)
                    wmma::mma_sync(c[i][j], a[i], b[j], c[i][j]);
        }
        __syncthreads();
    }

    /* epilogue: C -> smem (128 x 132 f32), then bias + leaky+residual, write h + hi/lo pack */
    float* Cs = (float*)smem;
#pragma unroll
    for (int i = 0; i < 2; i++)
#pragma unroll
        for (int j = 0; j < 4; j++)
            wmma::store_matrix_sync(Cs + (wm * 32 + i * 16) * 132 + wn * 64 + j * 16,
                                    c[i][j], 132, wmma::mem_row_major);
    __syncthreads();

#pragma unroll 1
    for (int it = 0; it < 16; it++) {
        int idx = tid + it * 256;          /* 0..4095 */
        int row = idx >> 5;                /* 0..127 */
        int c4 = (idx & 31) * 4;           /* 0..124 */
        int gr = bm + row;
        if (gr < NN) {
            float x0 = Cs[row * 132 + c4 + 0] + sbias[c4 + 0];
            float x1 = Cs[row * 132 + c4 + 1] + sbias[c4 + 1];
            float x2 = Cs[row * 132 + c4 + 2] + sbias[c4 + 2];
            float x3 = Cs[row * 132 + c4 + 3] + sbias[c4 + 3];
            x0 = (x0 > 0.0f) ? 2.0f * x0 : (1.0f + NEGS) * x0;
            x1 = (x1 > 0.0f) ? 2.0f * x1 : (1.0f + NEGS) * x1;
            x2 = (x2 > 0.0f) ? 2.0f * x2 : (1.0f + NEGS) * x2;
            x3 = (x3 > 0.0f) ? 2.0f * x3 : (1.0f + NEGS) * x3;
            int col = bn * 128 + c4;
            *(float4*)(g_h + (size_t)gr * 256 + col) = make_float4(x0, x1, x2, x3);
            __nv_bfloat16 h0 = __float2bfloat16(x0), h1 = __float2bfloat16(x1);
            __nv_bfloat16 h2 = __float2bfloat16(x2), h3 = __float2bfloat16(x3);
            uint2 hu, lu;
            hu.x = (uint32_t)__bfloat16_as_ushort(h0) | ((uint32_t)__bfloat16_as_ushort(h1) << 16);
            hu.y = (uint32_t)__bfloat16_as_ushort(h2) | ((uint32_t)__bfloat16_as_ushort(h3) << 16);
            __nv_bfloat16 q0 = __float2bfloat16(x0 - __bfloat162float(h0));
            __nv_bfloat16 q1 = __float2bfloat16(x1 - __bfloat162float(h1));
            __nv_bfloat16 q2 = __float2bfloat16(x2 - __bfloat162float(h2));
            __nv_bfloat16 q3 = __float2bfloat16(x3 - __bfloat162float(h3));
            lu.x = (uint32_t)__bfloat16_as_ushort(q0) | ((uint32_t)__bfloat16_as_ushort(q1) << 16);
            lu.y = (uint32_t)__bfloat16_as_ushort(q2) | ((uint32_t)__bfloat16_as_ushort(q3) << 16);
            *(uint2*)(hin_out + (size_t)gr * 512 + col) = hu;
            *(uint2*)(hin_out + (size_t)gr * 512 + 256 + col) = lu;
        }
    }
}

/* ---------------- GraphNorm + SoftmaxAggregation ---------------- */
__global__ void k_gn_softmax(const float* __restrict__ gw, const float* __restrict__ gb,
                             const float* __restrict__ gs, const float* __restrict__ tptr) {
    int b = blockIdx.x;
    int c = threadIdx.x;
    int start = g_gstart[b], cnt = g_gcnt[b];
    float cntf = (cnt > 0) ? (float)cnt : 1.0f;
    float t = tptr[0];

    float s = 0.0f;
    for (int i = 0; i < cnt; i++) s += g_h[(size_t)(start + i) * F2C + c];
    float ms = (s / cntf) * gs[c];

    float v = 0.0f;
    for (int i = 0; i < cnt; i++) {
        float o = g_h[(size_t)(start + i) * F2C + c] - ms;
        v += o * o;
    }
    float inv = 1.0f / sqrtf(v / cntf + EPSV);
    float w = gw[c], bias = gb[c];
    for (int i = 0; i < cnt; i++) {
        size_t idx = (size_t)(start + i) * F2C + c;
        g_h[idx] = w * (g_h[idx] - ms) * inv + bias;
    }

    float m = -FLT_MAX;
    for (int i = 0; i < cnt; i++) m = fmaxf(m, g_h[(size_t)(start + i) * F2C + c] * t);
    float se = 0.0f, sh = 0.0f;
    for (int i = 0; i < cnt; i++) {
        float hv = g_h[(size_t)(start + i) * F2C + c];
        float e = expf(hv * t - m);
        se += e;
        sh += e * hv;
    }
    g_g[b * F2C + c] = (cnt > 0) ? (sh / se) : 0.0f;
}

/* ---------------- MLP head ---------------- */
__global__ void k_mlp1(const float* __restrict__ W, const float* __restrict__ bias) {
    __shared__ float row[F2C];
    int b = blockIdx.x, j = threadIdx.x;
    row[j] = g_g[b * F2C + j];
    __syncthreads();
    float s = bias[j];
#pragma unroll 8
    for (int k = 0; k < F2C; k++) s += row[k] * W[k * F2C + j];
    g_y1[b * F2C + j] = (s > 0.0f) ? s : NEGS * s;
}

__global__ void k_mlp2(const float* __restrict__ W, const float* __restrict__ bias) {
    __shared__ float row[F2C];
    int b = blockIdx.x, j = threadIdx.x;
    row[j] = g_y1[b * F2C + j];
    row[j + 128] = g_y1[b * F2C + j + 128];
    __syncthreads();
    float s = bias[j];
#pragma unroll 8
    for (int k = 0; k < F2C; k++) s += row[k] * W[k * FF + j];
    g_y2[b * FF + j] = (s > 0.0f) ? s : NEGS * s;
}

__global__ void k_mlp3(const float* __restrict__ W, const float* __restrict__ bias,
                       float* __restrict__ out) {
    __shared__ float row[FF];
    int b = blockIdx.x, j = threadIdx.x;
    if (j < FF) row[j] = g_y2[b * FF + j];
    __syncthreads();
    float acc[8];
#pragma unroll
    for (int r = 0; r < 8; r++) {
        int idx = j + 256 * r;
        acc[r] = (idx < AA) ? bias[idx] : 0.0f;
    }
    for (int k = 0; k < FF; k++) {
        float rv = row[k];
        const float* wr = W + (size_t)k * AA;
#pragma unroll
        for (int r = 0; r < 8; r++) {
            int idx = j + 256 * r;
            if (idx < AA) acc[r] += rv * wr[idx];
        }
    }
#pragma unroll
    for (int r = 0; r < 8; r++) {
        int idx = j + 256 * r;
        if (idx < AA) out[b * AA + idx] = acc[r];
    }
}

/* ---------------- launch ---------------- */
extern "C" void kernel_launch(void* const* d_in, const int* in_sizes, int n_in,
                              void* d_out, int out_size) {
    const int*   x     = (const int*)d_in[0];
    const int*   ei    = (const int*)d_in[1];
    const int*   batch = (const int*)d_in[2];
    const float* emb   = (const float*)d_in[3];
    const float* Wl    = (const float*)d_in[4];
    const float* bl    = (const float*)d_in[5];
    const float* Wr    = (const float*)d_in[6];
    const float* gw    = (const float*)d_in[7];
    const float* gb    = (const float*)d_in[8];
    const float* gs    = (const float*)d_in[9];
    const float* t     = (const float*)d_in[10];
    const float* W1    = (const float*)d_in[11];
    const float* b1    = (const float*)d_in[12];
    const float* W2    = (const float*)d_in[13];
    const float* b2    = (const float*)d_in[14];
    const float* W3    = (const float*)d_in[15];
    const float* b3    = (const float*)d_in[16];
    float* out = (float*)d_out;

    cudaFuncSetAttribute(k_sage_wmma, cudaFuncAttributeMaxDynamicSharedMemorySize, SMEMB);

    __nv_bfloat16* hinbuf[2];
    cudaGetSymbolAddress((void**)&hinbuf[0], g_hinA);
    cudaGetSymbolAddress((void**)&hinbuf[1], g_hinB);

    /* graph structure + packing */
    k_zero<<<(NN + 255) / 256, 256>>>();
    k_embed<<<(NN * F2C + 255) / 256, 256>>>(x, emb);
    k_deg<<<(EE + 255) / 256, 256>>>(ei);
    k_scan_a<<<SCANB, 256>>>();
    k_scan_b<<<1, 256>>>();
    k_scan_c<<<(NN + 1 + 255) / 256, 256>>>();
    k_prep<<<(NN + 255) / 256, 256>>>();
    k_scatter<<<(EE + 255) / 256, 256>>>(ei);
    k_sortseg<<<(NN + 255) / 256, 256>>>();
    k_gcnt<<<(NN + 255) / 256, 256>>>(batch);
    k_gscan<<<1, BB>>>();
    k_bpack<<<(LL * 512 * 256 + 255) / 256, 256>>>(Wl, Wr);

    /* 10 SAGE layers on tensor cores (wmma / HMMA); hin ping-pong fixes the R3 race */
    dim3 ggrid(GX, 2);
    for (int l = 0; l < LL; l++) {
        k_aggregate<<<NN, F2C>>>();
        k_sage_wmma<<<ggrid, 256, SMEMB>>>(l, bl + l * F2C,
                                           hinbuf[l & 1], hinbuf[(l & 1) ^ 1]);
    }

    k_gn_softmax<<<BB, F2C>>>(gw, gb, gs, t);

    k_mlp1<<<BB, F2C>>>(W1, b1);
    k_mlp2<<<BB, FF>>>(W2, b2);
    k_mlp3<<<BB, 256>>>(W3, b3, out);
}

// round 5
// speedup vs baseline: 1.8093x; 1.2244x over previous
#include <cuda_runtime.h>
#include <cuda_bf16.h>
#include <math.h>
#include <float.h>
#include <stdint.h>

#define NN 50000
#define EE 300000
#define BB 256
#define FF 128
#define F2C 256
#define AA 2016
#define LL 10
#define NEGS 0.01f
#define EPSV 1e-5f

#define SCANB ((NN + 256) / 256)
#define MT 128
#define NB ((NN + MT - 1) / MT)     /* 391 node blocks */
#define NSTAGE 48                   /* K'' = 1536 = 48 * 32 */
#define SMEMB 69632                 /* 4 ring stages (64KB) vs epilogue 128x132 f32 (67.6KB) */

/* ---------------- scratch ----------------
   Slab layout for bf16 operands: chunk = [128 rows][32 k] = 8KB, SW64-swizzled.
   agg/hin: per node block nb, 16 chunks: j 0..7 = hi (k cols 32j..), j 8..15 = lo. */
__device__ float g_h[NN * F2C];
__device__ __nv_bfloat16 g_aggT[(size_t)NB * 16 * 4096];
__device__ __nv_bfloat16 g_hinA[(size_t)NB * 16 * 4096];
__device__ __nv_bfloat16 g_hinB[(size_t)NB * 16 * 4096];
__device__ __nv_bfloat16 g_Bpack[(size_t)LL * NSTAGE * 2 * 4096];  /* [l][s][bn][chunk 8KB] */
__device__ float g_invdeg[NN];
__device__ int   g_deg[NN];
__device__ int   g_off[NN + 1];
__device__ int   g_cur[NN];
__device__ int   g_srcs[EE];
__device__ int   g_gcnt[BB];
__device__ int   g_gstart[BB];
__device__ int   g_bsum[SCANB];
__device__ float g_g[BB * F2C];
__device__ float g_y1[BB * F2C];
__device__ float g_y2[BB * FF];

/* ---------------- helpers ---------------- */
__device__ __forceinline__ uint32_t smem_u32(const void* p) {
    uint32_t a;
    asm("{ .reg .u64 t; cvta.to.shared.u64 t, %1; cvt.u32.u64 %0, t; }" : "=r"(a) : "l"(p));
    return a;
}
/* byte offset of (row, kk) inside an 8KB slab chunk, SW64-swizzled (16B units). */
__device__ __host__ __forceinline__ uint32_t slab_off(int row, int kk) {
    int c = kk >> 3;
    return (uint32_t)(row * 64 + (((c ^ ((row & 6) >> 1))) << 4) + ((kk & 7) << 1));
}
__device__ __forceinline__ void mbar_init(uint32_t a, uint32_t cnt) {
    asm volatile("mbarrier.init.shared.b64 [%0], %1;" :: "r"(a), "r"(cnt) : "memory");
}
__device__ __forceinline__ void mbar_wait(uint32_t a, uint32_t parity) {
    asm volatile(
        "{\n\t.reg .pred P;\n"
        "W_%=:\n\t"
        "mbarrier.try_wait.parity.acquire.cta.shared::cta.b64 P, [%0], %1, 0x989680;\n\t"
        "@P bra.uni D_%=;\n\t"
        "bra.uni W_%=;\n"
        "D_%=:\n\t}"
        :: "r"(a), "r"(parity) : "memory");
}
__device__ __forceinline__ void mbar_expect(uint32_t a, uint32_t bytes) {
    asm volatile("mbarrier.arrive.expect_tx.shared.b64 _, [%0], %1;"
                 :: "r"(a), "r"(bytes) : "memory");
}
__device__ __forceinline__ void bulkcp(uint32_t dst, const void* src, uint32_t bytes, uint32_t mb) {
    asm volatile("cp.async.bulk.shared::cluster.global.mbarrier::complete_tx::bytes [%0], [%1], %2, [%3];"
                 :: "r"(dst), "l"(src), "r"(bytes), "r"(mb) : "memory");
}
#define LDSM4(r, addr) \
    asm volatile("ldmatrix.sync.aligned.m8n8.x4.shared.b16 {%0,%1,%2,%3}, [%4];" \
                 : "=r"((r)[0]), "=r"((r)[1]), "=r"((r)[2]), "=r"((r)[3]) : "r"(addr))
#define MMA16816(d, a, b0, b1) \
    asm volatile("mma.sync.aligned.m16n8k16.row.col.f32.bf16.bf16.f32 " \
                 "{%0,%1,%2,%3}, {%4,%5,%6,%7}, {%8,%9}, {%0,%1,%2,%3};" \
                 : "+f"((d)[0]), "+f"((d)[1]), "+f"((d)[2]), "+f"((d)[3]) \
                 : "r"((a)[0]), "r"((a)[1]), "r"((a)[2]), "r"((a)[3]), "r"(b0), "r"(b1))

/* ---------------- setup kernels ---------------- */
__global__ void k_zero() {
    int i = blockIdx.x * blockDim.x + threadIdx.x;
    if (i < NN) g_deg[i] = 0;
    if (i < BB) g_gcnt[i] = 0;
}

__global__ void k_embed(const int* __restrict__ x, const float* __restrict__ emb) {
    int idx = blockIdx.x * blockDim.x + threadIdx.x;
    if (idx >= NN * F2C) return;
    int node = idx >> 8;
    int c = idx & 255;
    int tok = x[node * 2 + (c >> 7)];
    float v = emb[tok * FF + (c & 127)];
    g_h[idx] = v;
    __nv_bfloat16 hi = __float2bfloat16(v);
    float lo = v - __bfloat162float(hi);
    size_t cb = ((size_t)(node >> 7) * 16 + (c >> 5)) * 8192;
    uint32_t off = slab_off(node & 127, c & 31);
    *(__nv_bfloat16*)((char*)g_hinA + cb + off) = hi;
    *(__nv_bfloat16*)((char*)g_hinA + cb + 8 * 8192 + off) = __float2bfloat16(lo);
}

__global__ void k_deg(const int* __restrict__ ei) {
    int e = blockIdx.x * blockDim.x + threadIdx.x;
    if (e < EE) atomicAdd(&g_deg[ei[EE + e]], 1);
}

__global__ void k_scan_a() {
    __shared__ int sh[256];
    int b = blockIdx.x, t = threadIdx.x;
    int i = b * 256 + t;
    int v = (i < NN) ? g_deg[i] : 0;
    sh[t] = v;
    __syncthreads();
    for (int o = 1; o < 256; o <<= 1) {
        int add = (t >= o) ? sh[t - o] : 0;
        __syncthreads();
        sh[t] += add;
        __syncthreads();
    }
    if (i <= NN) g_off[i] = sh[t] - v;
    if (t == 255) g_bsum[b] = sh[255];
}
__global__ void k_scan_b() {
    __shared__ int sh[256];
    int t = threadIdx.x;
    int v = (t < SCANB) ? g_bsum[t] : 0;
    sh[t] = v;
    __syncthreads();
    for (int o = 1; o < 256; o <<= 1) {
        int add = (t >= o) ? sh[t - o] : 0;
        __syncthreads();
        sh[t] += add;
        __syncthreads();
    }
    if (t < SCANB) g_bsum[t] = sh[t] - v;
}
__global__ void k_scan_c() {
    int i = blockIdx.x * blockDim.x + threadIdx.x;
    if (i <= NN) g_off[i] += g_bsum[i >> 8];
}

__global__ void k_prep() {
    int i = blockIdx.x * blockDim.x + threadIdx.x;
    if (i >= NN) return;
    g_cur[i] = g_off[i];
    int d = g_deg[i];
    g_invdeg[i] = 1.0f / (float)(d > 0 ? d : 1);
}

__global__ void k_scatter(const int* __restrict__ ei) {
    int e = blockIdx.x * blockDim.x + threadIdx.x;
    if (e >= EE) return;
    int d = ei[EE + e];
    int pos = atomicAdd(&g_cur[d], 1);
    g_srcs[pos] = ei[e];
}

__global__ void k_sortseg() {
    int n = blockIdx.x * blockDim.x + threadIdx.x;
    if (n >= NN) return;
    int beg = g_off[n], end = g_off[n + 1];
    for (int i = beg + 1; i < end; i++) {
        int v = g_srcs[i];
        int j = i - 1;
        while (j >= beg && g_srcs[j] > v) { g_srcs[j + 1] = g_srcs[j]; j--; }
        g_srcs[j + 1] = v;
    }
}

__global__ void k_gcnt(const int* __restrict__ batch) {
    int i = blockIdx.x * blockDim.x + threadIdx.x;
    if (i < NN) atomicAdd(&g_gcnt[batch[i]], 1);
}

__global__ void k_gscan() {
    __shared__ int sh[BB];
    int tid = threadIdx.x;
    sh[tid] = g_gcnt[tid];
    __syncthreads();
    for (int ofs = 1; ofs < BB; ofs <<= 1) {
        int add = (tid >= ofs) ? sh[tid - ofs] : 0;
        __syncthreads();
        sh[tid] += add;
        __syncthreads();
    }
    g_gstart[tid] = sh[tid] - g_gcnt[tid];
}

/* B pack into per-stage swizzled chunks.
   Stage s covers k'' = 32s..32s+31; mapping k''->(hi/lo, k in [0,512)):
   k''<512: hi(W(k'')); [512,1024): hi(W(k''-512)); [1024,1536): lo(W(k''-1024)).
   W(k) = k<256 ? Wl[k][n] : Wr[k-256][n]. */
__global__ void k_bpack(const float* __restrict__ Wl, const float* __restrict__ Wr) {
    int idx = blockIdx.x * blockDim.x + threadIdx.x;
    if (idx >= LL * NSTAGE * 2 * 4096) return;
    int kk = idx & 31;
    int row = (idx >> 5) & 127;
    int bn = (idx >> 12) & 1;
    int rest = idx >> 13;
    int s = rest % NSTAGE;
    int l = rest / NSTAGE;
    int kpp = s * 32 + kk;
    int lo = kpp >= 1024;
    int k = kpp - (kpp >= 512 ? 512 : 0) - (kpp >= 1024 ? 512 : 0);
    int n = bn * 128 + row;
    float w = (k < 256) ? Wl[((size_t)l * 256 + k) * 256 + n]
                        : Wr[((size_t)l * 256 + (k - 256)) * 256 + n];
    __nv_bfloat16 hi = __float2bfloat16(w);
    __nv_bfloat16 val = lo ? __float2bfloat16(w - __bfloat162float(hi)) : hi;
    size_t cb = ((size_t)((l * NSTAGE + s) * 2 + bn)) * 8192;
    *(__nv_bfloat16*)((char*)g_Bpack + cb + slab_off(row, kk)) = val;
}

/* mean-aggregate neighbors -> hi/lo bf16 into g_aggT slab layout */
__global__ void k_aggregate() {
    int n = blockIdx.x;
    int c = threadIdx.x;
    int beg = g_off[n], end = g_off[n + 1];
    float s = 0.0f;
    for (int i = beg; i < end; i++) s += g_h[(size_t)g_srcs[i] * F2C + c];
    float a = s * g_invdeg[n];
    __nv_bfloat16 hi = __float2bfloat16(a);
    float lo = a - __bfloat162float(hi);
    size_t cb = ((size_t)(n >> 7) * 16 + (c >> 5)) * 8192;
    uint32_t off = slab_off(n & 127, c & 31);
    *(__nv_bfloat16*)((char*)g_aggT + cb + off) = hi;
    *(__nv_bfloat16*)((char*)g_aggT + cb + 8 * 8192 + off) = __float2bfloat16(lo);
}

/* ---------------- SAGE GEMM: bulk-copy pipeline + ldmatrix/mma ----------------
   C[128,128] = A''[128,1536] @ B''[1536,128], grid (391, 2).
   Stage = K32: A chunk 8KB + B chunk 8KB, 4-deep mbarrier ring.
   Stage s -> A source: seg=s>>3: {agg_hi, hin_hi, agg_lo, hin_lo, agg_hi, hin_hi}. */
__global__ __launch_bounds__(256, 2)
void k_sage_mma(int layer, const float* __restrict__ bl,
                const __nv_bfloat16* __restrict__ hin_in,
                __nv_bfloat16* __restrict__ hin_out) {
    extern __shared__ char smem[];
    __shared__ float sbias[128];
    __shared__ __align__(8) unsigned long long mbar[4];
    const int tid = threadIdx.x;
    const int nb = blockIdx.x;
    const int bm = nb * MT;
    const int bn = blockIdx.y;
    const uint32_t sb = smem_u32(smem);

    if (tid == 0) {
#pragma unroll
        for (int i = 0; i < 4; i++) mbar_init(smem_u32(&mbar[i]), 1);
    }
    if (tid < 128) sbias[tid] = bl[bn * 128 + tid];
    __syncthreads();

    auto issue = [&](int s) {
        int b = s & 3;
        uint32_t mb = smem_u32(&mbar[b]);
        mbar_expect(mb, 16384);
        int seg = s >> 3;
        int j = (s & 7) + (((seg >> 1) == 1) ? 8 : 0);
        const __nv_bfloat16* asrc = ((seg & 1) ? hin_in : g_aggT) + ((size_t)(nb * 16 + j)) * 4096;
        bulkcp(sb + b * 16384, asrc, 8192, mb);
        const __nv_bfloat16* bsrc = g_Bpack + ((size_t)((layer * NSTAGE + s) * 2 + bn)) * 4096;
        bulkcp(sb + b * 16384 + 8192, bsrc, 8192, mb);
    };
    if (tid == 0) {
#pragma unroll
        for (int s = 0; s < 4; s++) issue(s);
    }

    const int wid = tid >> 5, l = tid & 31;
    const int wm = wid >> 1;       /* 0..3: m 32-block */
    const int wn = wid & 1;        /* 0..1: n 64-block */
    const int rowlane = l & 15;
    const int c16 = l >> 4;

    float acc[2][8][4];
#pragma unroll
    for (int i = 0; i < 2; i++)
#pragma unroll
        for (int j = 0; j < 8; j++)
#pragma unroll
            for (int q = 0; q < 4; q++) acc[i][j][q] = 0.0f;

    for (int s = 0; s < NSTAGE; s++) {
        int b = s & 3;
        mbar_wait(smem_u32(&mbar[b]), (s >> 2) & 1);
        uint32_t Abase = sb + b * 16384;
        uint32_t Bbase = Abase + 8192;
#pragma unroll
        for (int ks = 0; ks < 2; ks++) {
            uint32_t a[2][4], bb[4][4];
#pragma unroll
            for (int mi = 0; mi < 2; mi++) {
                int row = wm * 32 + mi * 16 + rowlane;
                int c = ks * 2 + c16;
                LDSM4(a[mi], Abase + row * 64 + ((c ^ ((row & 6) >> 1)) << 4));
            }
#pragma unroll
            for (int nj = 0; nj < 4; nj++) {
                int row = wn * 64 + nj * 16 + rowlane;
                int c = ks * 2 + c16;
                LDSM4(bb[nj], Bbase + row * 64 + ((c ^ ((row & 6) >> 1)) << 4));
            }
#pragma unroll
            for (int mi = 0; mi < 2; mi++)
#pragma unroll
                for (int nj = 0; nj < 4; nj++) {
                    MMA16816(acc[mi][nj * 2], a[mi], bb[nj][0], bb[nj][2]);
                    MMA16816(acc[mi][nj * 2 + 1], a[mi], bb[nj][1], bb[nj][3]);
                }
        }
        __syncthreads();
        if (tid == 0 && s + 4 < NSTAGE) issue(s + 4);
    }

    /* epilogue: acc -> smem Cs[128][132], then bias + leaky+residual, write h + hin slabs */
    float* Cs = (float*)smem;
#pragma unroll
    for (int mi = 0; mi < 2; mi++)
#pragma unroll
        for (int jn = 0; jn < 8; jn++) {
            int r1 = wm * 32 + mi * 16 + (l >> 2);
            int cc = wn * 64 + jn * 8 + (l & 3) * 2;
            Cs[r1 * 132 + cc]       = acc[mi][jn][0];
            Cs[r1 * 132 + cc + 1]   = acc[mi][jn][1];
            Cs[(r1 + 8) * 132 + cc]     = acc[mi][jn][2];
            Cs[(r1 + 8) * 132 + cc + 1] = acc[mi][jn][3];
        }
    __syncthreads();

#pragma unroll 1
    for (int it = 0; it < 16; it++) {
        int idx = tid + it * 256;
        int row = idx >> 5;
        int c4 = (idx & 31) * 4;
        int gr = bm + row;
        if (gr < NN) {
            float x0 = Cs[row * 132 + c4 + 0] + sbias[c4 + 0];
            float x1 = Cs[row * 132 + c4 + 1] + sbias[c4 + 1];
            float x2 = Cs[row * 132 + c4 + 2] + sbias[c4 + 2];
            float x3 = Cs[row * 132 + c4 + 3] + sbias[c4 + 3];
            x0 = (x0 > 0.0f) ? 2.0f * x0 : (1.0f + NEGS) * x0;
            x1 = (x1 > 0.0f) ? 2.0f * x1 : (1.0f + NEGS) * x1;
            x2 = (x2 > 0.0f) ? 2.0f * x2 : (1.0f + NEGS) * x2;
            x3 = (x3 > 0.0f) ? 2.0f * x3 : (1.0f + NEGS) * x3;
            int col = bn * 128 + c4;
            *(float4*)(g_h + (size_t)gr * 256 + col) = make_float4(x0, x1, x2, x3);
            __nv_bfloat16 h0 = __float2bfloat16(x0), h1 = __float2bfloat16(x1);
            __nv_bfloat16 h2 = __float2bfloat16(x2), h3 = __float2bfloat16(x3);
            uint2 hu, lu;
            hu.x = (uint32_t)__bfloat16_as_ushort(h0) | ((uint32_t)__bfloat16_as_ushort(h1) << 16);
            hu.y = (uint32_t)__bfloat16_as_ushort(h2) | ((uint32_t)__bfloat16_as_ushort(h3) << 16);
            __nv_bfloat16 q0 = __float2bfloat16(x0 - __bfloat162float(h0));
            __nv_bfloat16 q1 = __float2bfloat16(x1 - __bfloat162float(h1));
            __nv_bfloat16 q2 = __float2bfloat16(x2 - __bfloat162float(h2));
            __nv_bfloat16 q3 = __float2bfloat16(x3 - __bfloat162float(h3));
            lu.x = (uint32_t)__bfloat16_as_ushort(q0) | ((uint32_t)__bfloat16_as_ushort(q1) << 16);
            lu.y = (uint32_t)__bfloat16_as_ushort(q2) | ((uint32_t)__bfloat16_as_ushort(q3) << 16);
            size_t cb = ((size_t)(gr >> 7) * 16 + (col >> 5)) * 8192;
            uint32_t off = slab_off(gr & 127, col & 31);
            *(uint2*)((char*)hin_out + cb + off) = hu;
            *(uint2*)((char*)hin_out + cb + 8 * 8192 + off) = lu;
        }
    }
}

/* ---------------- GraphNorm + SoftmaxAggregation ---------------- */
__global__ void k_gn_softmax(const float* __restrict__ gw, const float* __restrict__ gb,
                             const float* __restrict__ gs, const float* __restrict__ tptr) {
    int b = blockIdx.x;
    int c = threadIdx.x;
    int start = g_gstart[b], cnt = g_gcnt[b];
    float cntf = (cnt > 0) ? (float)cnt : 1.0f;
    float t = tptr[0];

    float s = 0.0f;
    for (int i = 0; i < cnt; i++) s += g_h[(size_t)(start + i) * F2C + c];
    float ms = (s / cntf) * gs[c];

    float v = 0.0f;
    for (int i = 0; i < cnt; i++) {
        float o = g_h[(size_t)(start + i) * F2C + c] - ms;
        v += o * o;
    }
    float inv = 1.0f / sqrtf(v / cntf + EPSV);
    float w = gw[c], bias = gb[c];
    for (int i = 0; i < cnt; i++) {
        size_t idx = (size_t)(start + i) * F2C + c;
        g_h[idx] = w * (g_h[idx] - ms) * inv + bias;
    }

    float m = -FLT_MAX;
    for (int i = 0; i < cnt; i++) m = fmaxf(m, g_h[(size_t)(start + i) * F2C + c] * t);
    float se = 0.0f, sh = 0.0f;
    for (int i = 0; i < cnt; i++) {
        float hv = g_h[(size_t)(start + i) * F2C + c];
        float e = expf(hv * t - m);
        se += e;
        sh += e * hv;
    }
    g_g[b * F2C + c] = (cnt > 0) ? (sh / se) : 0.0f;
}

/* ---------------- MLP head ---------------- */
__global__ void k_mlp1(const float* __restrict__ W, const float* __restrict__ bias) {
    __shared__ float row[F2C];
    int b = blockIdx.x, j = threadIdx.x;
    row[j] = g_g[b * F2C + j];
    __syncthreads();
    float s = bias[j];
#pragma unroll 8
    for (int k = 0; k < F2C; k++) s += row[k] * W[k * F2C + j];
    g_y1[b * F2C + j] = (s > 0.0f) ? s : NEGS * s;
}

__global__ void k_mlp2(const float* __restrict__ W, const float* __restrict__ bias) {
    __shared__ float row[F2C];
    int b = blockIdx.x, j = threadIdx.x;
    row[j] = g_y1[b * F2C + j];
    row[j + 128] = g_y1[b * F2C + j + 128];
    __syncthreads();
    float s = bias[j];
#pragma unroll 8
    for (int k = 0; k < F2C; k++) s += row[k] * W[k * FF + j];
    g_y2[b * FF + j] = (s > 0.0f) ? s : NEGS * s;
}

__global__ void k_mlp3(const float* __restrict__ W, const float* __restrict__ bias,
                       float* __restrict__ out) {
    __shared__ float row[FF];
    int b = blockIdx.x, j = threadIdx.x;
    if (j < FF) row[j] = g_y2[b * FF + j];
    __syncthreads();
    float acc[8];
#pragma unroll
    for (int r = 0; r < 8; r++) {
        int idx = j + 256 * r;
        acc[r] = (idx < AA) ? bias[idx] : 0.0f;
    }
    for (int k = 0; k < FF; k++) {
        float rv = row[k];
        const float* wr = W + (size_t)k * AA;
#pragma unroll
        for (int r = 0; r < 8; r++) {
            int idx = j + 256 * r;
            if (idx < AA) acc[r] += rv * wr[idx];
        }
    }
#pragma unroll
    for (int r = 0; r < 8; r++) {
        int idx = j + 256 * r;
        if (idx < AA) out[b * AA + idx] = acc[r];
    }
}

/* ---------------- launch ---------------- */
extern "C" void kernel_launch(void* const* d_in, const int* in_sizes, int n_in,
                              void* d_out, int out_size) {
    const int*   x     = (const int*)d_in[0];
    const int*   ei    = (const int*)d_in[1];
    const int*   batch = (const int*)d_in[2];
    const float* emb   = (const float*)d_in[3];
    const float* Wl    = (const float*)d_in[4];
    const float* bl    = (const float*)d_in[5];
    const float* Wr    = (const float*)d_in[6];
    const float* gw    = (const float*)d_in[7];
    const float* gb    = (const float*)d_in[8];
    const float* gs    = (const float*)d_in[9];
    const float* t     = (const float*)d_in[10];
    const float* W1    = (const float*)d_in[11];
    const float* b1    = (const float*)d_in[12];
    const float* W2    = (const float*)d_in[13];
    const float* b2    = (const float*)d_in[14];
    const float* W3    = (const float*)d_in[15];
    const float* b3    = (const float*)d_in[16];
    float* out = (float*)d_out;

    cudaFuncSetAttribute(k_sage_mma, cudaFuncAttributeMaxDynamicSharedMemorySize, SMEMB);

    __nv_bfloat16* hinbuf[2];
    cudaGetSymbolAddress((void**)&hinbuf[0], g_hinA);
    cudaGetSymbolAddress((void**)&hinbuf[1], g_hinB);

    /* graph structure + packing */
    k_zero<<<(NN + 255) / 256, 256>>>();
    k_embed<<<(NN * F2C + 255) / 256, 256>>>(x, emb);
    k_deg<<<(EE + 255) / 256, 256>>>(ei);
    k_scan_a<<<SCANB, 256>>>();
    k_scan_b<<<1, 256>>>();
    k_scan_c<<<(NN + 1 + 255) / 256, 256>>>();
    k_prep<<<(NN + 255) / 256, 256>>>();
    k_scatter<<<(EE + 255) / 256, 256>>>(ei);
    k_sortseg<<<(NN + 255) / 256, 256>>>();
    k_gcnt<<<(NN + 255) / 256, 256>>>(batch);
    k_gscan<<<1, BB>>>();
    k_bpack<<<(LL * NSTAGE * 2 * 4096 + 255) / 256, 256>>>(Wl, Wr);

    /* 10 SAGE layers: bulk-copy pipelined tensor-core GEMM */
    dim3 ggrid(NB, 2);
    for (int l = 0; l < LL; l++) {
        k_aggregate<<<NN, F2C>>>();
        k_sage_mma<<<ggrid, 256, SMEMB>>>(l, bl + l * F2C,
                                          hinbuf[l & 1], hinbuf[(l & 1) ^ 1]);
    }

    k_gn_softmax<<<BB, F2C>>>(gw, gb, gs, t);

    k_mlp1<<<BB, F2C>>>(W1, b1);
    k_mlp2<<<BB, FF>>>(W2, b2);
    k_mlp3<<<BB, 256>>>(W3, b3, out);
}

// round 6
// speedup vs baseline: 2.2428x; 1.2395x over previous
#include <cuda_runtime.h>
#include <cuda_bf16.h>
#include <math.h>
#include <float.h>
#include <stdint.h>

#define NN 50000
#define EE 300000
#define BB 256
#define FF 128
#define F2C 256
#define AA 2016
#define LL 10
#define NEGS 0.01f
#define EPSV 1e-5f

#define SCANB ((NN + 256) / 256)
#define MT 128
#define NB ((NN + MT - 1) / MT)     /* 391 node blocks */
#define NSTAGE 48                   /* K'' = 1536 = 48 * 32 */
#define NSLOT 6                     /* smem ring slots (16KB each) */
#define SMEMB (NSLOT * 16384)       /* 96KB dyn smem; epilogue Cs (67.6KB) fits */

/* ---------------- scratch ----------------
   Slab layout for bf16 operands: chunk = [128 rows][32 k] = 8KB, SW64-swizzled.
   agg/hin: per node block nb, 16 chunks: j 0..7 = hi (k cols 32j..), j 8..15 = lo. */
__device__ float g_h[NN * F2C];
__device__ __nv_bfloat16 g_aggT[(size_t)NB * 16 * 4096];
__device__ __nv_bfloat16 g_hinA[(size_t)NB * 16 * 4096];
__device__ __nv_bfloat16 g_hinB[(size_t)NB * 16 * 4096];
__device__ __nv_bfloat16 g_Bpack[(size_t)LL * NSTAGE * 2 * 4096];  /* [l][s][bn][chunk 8KB] */
__device__ float g_invdeg[NN];
__device__ int   g_deg[NN];
__device__ int   g_off[NN + 1];
__device__ int   g_cur[NN];
__device__ int   g_srcs[EE];
__device__ int   g_gcnt[BB];
__device__ int   g_gstart[BB];
__device__ int   g_bsum[SCANB];
__device__ float g_g[BB * F2C];
__device__ float g_y1[BB * F2C];
__device__ float g_y2[BB * FF];

/* ---------------- helpers ---------------- */
__device__ __forceinline__ uint32_t smem_u32(const void* p) {
    uint32_t a;
    asm("{ .reg .u64 t; cvta.to.shared.u64 t, %1; cvt.u32.u64 %0, t; }" : "=r"(a) : "l"(p));
    return a;
}
/* byte offset of (row, kk) inside an 8KB slab chunk, SW64-swizzled (16B units). */
__device__ __host__ __forceinline__ uint32_t slab_off(int row, int kk) {
    int c = kk >> 3;
    return (uint32_t)(row * 64 + (((c ^ ((row & 6) >> 1))) << 4) + ((kk & 7) << 1));
}
__device__ __forceinline__ void mbar_init(uint32_t a, uint32_t cnt) {
    asm volatile("mbarrier.init.shared.b64 [%0], %1;" :: "r"(a), "r"(cnt) : "memory");
}
__device__ __forceinline__ void mbar_wait(uint32_t a, uint32_t parity) {
    asm volatile(
        "{\n\t.reg .pred P;\n"
        "W_%=:\n\t"
        "mbarrier.try_wait.parity.acquire.cta.shared::cta.b64 P, [%0], %1, 0x989680;\n\t"
        "@P bra.uni D_%=;\n\t"
        "bra.uni W_%=;\n"
        "D_%=:\n\t}"
        :: "r"(a), "r"(parity) : "memory");
}
__device__ __forceinline__ void mbar_arrive(uint32_t a) {
    asm volatile("mbarrier.arrive.shared.b64 _, [%0];" :: "r"(a) : "memory");
}
__device__ __forceinline__ void mbar_expect(uint32_t a, uint32_t bytes) {
    asm volatile("mbarrier.arrive.expect_tx.shared.b64 _, [%0], %1;"
                 :: "r"(a), "r"(bytes) : "memory");
}
__device__ __forceinline__ void bulkcp(uint32_t dst, const void* src, uint32_t bytes, uint32_t mb) {
    asm volatile("cp.async.bulk.shared::cluster.global.mbarrier::complete_tx::bytes [%0], [%1], %2, [%3];"
                 :: "r"(dst), "l"(src), "r"(bytes), "r"(mb) : "memory");
}
#define LDSM4(r, addr) \
    asm volatile("ldmatrix.sync.aligned.m8n8.x4.shared.b16 {%0,%1,%2,%3}, [%4];" \
                 : "=r"((r)[0]), "=r"((r)[1]), "=r"((r)[2]), "=r"((r)[3]) : "r"(addr))
#define MMA16816(d, a, b0, b1) \
    asm volatile("mma.sync.aligned.m16n8k16.row.col.f32.bf16.bf16.f32 " \
                 "{%0,%1,%2,%3}, {%4,%5,%6,%7}, {%8,%9}, {%0,%1,%2,%3};" \
                 : "+f"((d)[0]), "+f"((d)[1]), "+f"((d)[2]), "+f"((d)[3]) \
                 : "r"((a)[0]), "r"((a)[1]), "r"((a)[2]), "r"((a)[3]), "r"(b0), "r"(b1))

/* ---------------- setup kernels ---------------- */
__global__ void k_zero() {
    int i = blockIdx.x * blockDim.x + threadIdx.x;
    if (i < NN) g_deg[i] = 0;
    if (i < BB) g_gcnt[i] = 0;
}

__global__ void k_embed(const int* __restrict__ x, const float* __restrict__ emb) {
    int idx = blockIdx.x * blockDim.x + threadIdx.x;
    if (idx >= NN * F2C) return;
    int node = idx >> 8;
    int c = idx & 255;
    int tok = x[node * 2 + (c >> 7)];
    float v = emb[tok * FF + (c & 127)];
    g_h[idx] = v;
    __nv_bfloat16 hi = __float2bfloat16(v);
    float lo = v - __bfloat162float(hi);
    size_t cb = ((size_t)(node >> 7) * 16 + (c >> 5)) * 8192;
    uint32_t off = slab_off(node & 127, c & 31);
    *(__nv_bfloat16*)((char*)g_hinA + cb + off) = hi;
    *(__nv_bfloat16*)((char*)g_hinA + cb + 8 * 8192 + off) = __float2bfloat16(lo);
}

__global__ void k_deg(const int* __restrict__ ei) {
    int e = blockIdx.x * blockDim.x + threadIdx.x;
    if (e < EE) atomicAdd(&g_deg[ei[EE + e]], 1);
}

__global__ void k_scan_a() {
    __shared__ int sh[256];
    int b = blockIdx.x, t = threadIdx.x;
    int i = b * 256 + t;
    int v = (i < NN) ? g_deg[i] : 0;
    sh[t] = v;
    __syncthreads();
    for (int o = 1; o < 256; o <<= 1) {
        int add = (t >= o) ? sh[t - o] : 0;
        __syncthreads();
        sh[t] += add;
        __syncthreads();
    }
    if (i <= NN) g_off[i] = sh[t] - v;
    if (t == 255) g_bsum[b] = sh[255];
}
__global__ void k_scan_b() {
    __shared__ int sh[256];
    int t = threadIdx.x;
    int v = (t < SCANB) ? g_bsum[t] : 0;
    sh[t] = v;
    __syncthreads();
    for (int o = 1; o < 256; o <<= 1) {
        int add = (t >= o) ? sh[t - o] : 0;
        __syncthreads();
        sh[t] += add;
        __syncthreads();
    }
    if (t < SCANB) g_bsum[t] = sh[t] - v;
}
__global__ void k_scan_c() {
    int i = blockIdx.x * blockDim.x + threadIdx.x;
    if (i <= NN) g_off[i] += g_bsum[i >> 8];
}

__global__ void k_prep() {
    int i = blockIdx.x * blockDim.x + threadIdx.x;
    if (i >= NN) return;
    g_cur[i] = g_off[i];
    int d = g_deg[i];
    g_invdeg[i] = 1.0f / (float)(d > 0 ? d : 1);
}

__global__ void k_scatter(const int* __restrict__ ei) {
    int e = blockIdx.x * blockDim.x + threadIdx.x;
    if (e >= EE) return;
    int d = ei[EE + e];
    int pos = atomicAdd(&g_cur[d], 1);
    g_srcs[pos] = ei[e];
}

__global__ void k_sortseg() {
    int n = blockIdx.x * blockDim.x + threadIdx.x;
    if (n >= NN) return;
    int beg = g_off[n], end = g_off[n + 1];
    for (int i = beg + 1; i < end; i++) {
        int v = g_srcs[i];
        int j = i - 1;
        while (j >= beg && g_srcs[j] > v) { g_srcs[j + 1] = g_srcs[j]; j--; }
        g_srcs[j + 1] = v;
    }
}

__global__ void k_gcnt(const int* __restrict__ batch) {
    int i = blockIdx.x * blockDim.x + threadIdx.x;
    if (i < NN) atomicAdd(&g_gcnt[batch[i]], 1);
}

__global__ void k_gscan() {
    __shared__ int sh[BB];
    int tid = threadIdx.x;
    sh[tid] = g_gcnt[tid];
    __syncthreads();
    for (int ofs = 1; ofs < BB; ofs <<= 1) {
        int add = (tid >= ofs) ? sh[tid - ofs] : 0;
        __syncthreads();
        sh[tid] += add;
        __syncthreads();
    }
    g_gstart[tid] = sh[tid] - g_gcnt[tid];
}

/* B pack into per-stage swizzled chunks. */
__global__ void k_bpack(const float* __restrict__ Wl, const float* __restrict__ Wr) {
    int idx = blockIdx.x * blockDim.x + threadIdx.x;
    if (idx >= LL * NSTAGE * 2 * 4096) return;
    int kk = idx & 31;
    int row = (idx >> 5) & 127;
    int bn = (idx >> 12) & 1;
    int rest = idx >> 13;
    int s = rest % NSTAGE;
    int l = rest / NSTAGE;
    int kpp = s * 32 + kk;
    int lo = kpp >= 1024;
    int k = kpp - (kpp >= 512 ? 512 : 0) - (kpp >= 1024 ? 512 : 0);
    int n = bn * 128 + row;
    float w = (k < 256) ? Wl[((size_t)l * 256 + k) * 256 + n]
                        : Wr[((size_t)l * 256 + (k - 256)) * 256 + n];
    __nv_bfloat16 hi = __float2bfloat16(w);
    __nv_bfloat16 val = lo ? __float2bfloat16(w - __bfloat162float(hi)) : hi;
    size_t cb = ((size_t)((l * NSTAGE + s) * 2 + bn)) * 8192;
    *(__nv_bfloat16*)((char*)g_Bpack + cb + slab_off(row, kk)) = val;
}

/* mean-aggregate neighbors -> hi/lo bf16 into g_aggT slab layout (128 thr, 2 ch each) */
__global__ void k_aggregate() {
    int n = blockIdx.x;
    int t = threadIdx.x;       /* 0..127 */
    int c = t * 2;
    int beg = g_off[n], end = g_off[n + 1];
    float s0 = 0.0f, s1 = 0.0f;
    for (int i = beg; i < end; i++) {
        float2 v = *(const float2*)(g_h + (size_t)g_srcs[i] * F2C + c);
        s0 += v.x;
        s1 += v.y;
    }
    float inv = g_invdeg[n];
    float a0 = s0 * inv, a1 = s1 * inv;
    __nv_bfloat16 h0 = __float2bfloat16(a0), h1 = __float2bfloat16(a1);
    __nv_bfloat16 l0 = __float2bfloat16(a0 - __bfloat162float(h0));
    __nv_bfloat16 l1 = __float2bfloat16(a1 - __bfloat162float(h1));
    uint32_t hp = (uint32_t)__bfloat16_as_ushort(h0) | ((uint32_t)__bfloat16_as_ushort(h1) << 16);
    uint32_t lp = (uint32_t)__bfloat16_as_ushort(l0) | ((uint32_t)__bfloat16_as_ushort(l1) << 16);
    size_t cb = ((size_t)(n >> 7) * 16 + (c >> 5)) * 8192;
    uint32_t off = slab_off(n & 127, c & 31);
    *(uint32_t*)((char*)g_aggT + cb + off) = hp;
    *(uint32_t*)((char*)g_aggT + cb + 8 * 8192 + off) = lp;
}

/* ---------------- SAGE GEMM: warp-specialized producer + mbarrier ring ----------------
   C[128,128] = A''[128,1536] @ B''[1536,128], grid (391, 2).
   Warps 0..7 compute; warp 8 issues bulk copies. 6-slot ring, full/empty mbarriers. */
__global__ __launch_bounds__(288, 2)
void k_sage_mma(int layer, const float* __restrict__ bl,
                const __nv_bfloat16* __restrict__ hin_in,
                __nv_bfloat16* __restrict__ hin_out) {
    extern __shared__ char smem[];
    __shared__ float sbias[128];
    __shared__ __align__(8) unsigned long long mb_full[NSLOT], mb_empty[NSLOT];
    const int tid = threadIdx.x;
    const int wid = tid >> 5;
    const int lane = tid & 31;
    const int nb = blockIdx.x;
    const int bm = nb * MT;
    const int bn = blockIdx.y;
    const uint32_t sb = smem_u32(smem);

    if (tid == 0) {
#pragma unroll
        for (int i = 0; i < NSLOT; i++) {
            mbar_init(smem_u32(&mb_full[i]), 1);
            mbar_init(smem_u32(&mb_empty[i]), 8);
        }
    }
    if (tid < 128) sbias[tid] = bl[bn * 128 + tid];
    __syncthreads();

    if (wid == 8) {
        /* producer warp: one elected thread issues all copies */
        if (lane == 0) {
            int slot = 0, pe = 1;       /* empty-wait parity for slot (after first wrap -> 0) */
            for (int s = 0; s < NSTAGE; s++) {
                if (s >= NSLOT) mbar_wait(smem_u32(&mb_empty[slot]), pe);
                uint32_t mb = smem_u32(&mb_full[slot]);
                mbar_expect(mb, 16384);
                int seg = s >> 3;
                int j = (s & 7) + (((seg >> 1) == 1) ? 8 : 0);
                const __nv_bfloat16* asrc =
                    ((seg & 1) ? hin_in : g_aggT) + ((size_t)(nb * 16 + j)) * 4096;
                bulkcp(sb + slot * 16384, asrc, 8192, mb);
                const __nv_bfloat16* bsrc =
                    g_Bpack + ((size_t)((layer * NSTAGE + s) * 2 + bn)) * 4096;
                bulkcp(sb + slot * 16384 + 8192, bsrc, 8192, mb);
                if (++slot == NSLOT) { slot = 0; pe ^= 1; }
            }
        }
    } else {
        const int wm = wid >> 1;       /* 0..3: m 32-block */
        const int wn = wid & 1;        /* 0..1: n 64-block */
        const int rowlane = lane & 15;
        const int c16 = lane >> 4;

        float acc[2][8][4];
#pragma unroll
        for (int i = 0; i < 2; i++)
#pragma unroll
            for (int j = 0; j < 8; j++)
#pragma unroll
                for (int q = 0; q < 4; q++) acc[i][j][q] = 0.0f;

        int slot = 0, pf = 0;
        for (int s = 0; s < NSTAGE; s++) {
            mbar_wait(smem_u32(&mb_full[slot]), pf);
            uint32_t Abase = sb + slot * 16384;
            uint32_t Bbase = Abase + 8192;
#pragma unroll
            for (int ks = 0; ks < 2; ks++) {
                uint32_t a[2][4], bb[4][4];
#pragma unroll
                for (int mi = 0; mi < 2; mi++) {
                    int row = wm * 32 + mi * 16 + rowlane;
                    int c = ks * 2 + c16;
                    LDSM4(a[mi], Abase + row * 64 + ((c ^ ((row & 6) >> 1)) << 4));
                }
#pragma unroll
                for (int nj = 0; nj < 4; nj++) {
                    int row = wn * 64 + nj * 16 + rowlane;
                    int c = ks * 2 + c16;
                    LDSM4(bb[nj], Bbase + row * 64 + ((c ^ ((row & 6) >> 1)) << 4));
                }
#pragma unroll
                for (int mi = 0; mi < 2; mi++)
#pragma unroll
                    for (int nj = 0; nj < 4; nj++) {
                        MMA16816(acc[mi][nj * 2], a[mi], bb[nj][0], bb[nj][2]);
                        MMA16816(acc[mi][nj * 2 + 1], a[mi], bb[nj][1], bb[nj][3]);
                    }
            }
            if (lane == 0) mbar_arrive(smem_u32(&mb_empty[slot]));
            if (++slot == NSLOT) { slot = 0; pf ^= 1; }
        }

        /* stash acc -> smem after all-warp sync (below) */
        __syncthreads();
        float* Cs = (float*)smem;
#pragma unroll
        for (int mi = 0; mi < 2; mi++)
#pragma unroll
            for (int jn = 0; jn < 8; jn++) {
                int r1 = wm * 32 + mi * 16 + (lane >> 2);
                int cc = wn * 64 + jn * 8 + (lane & 3) * 2;
                Cs[r1 * 132 + cc]           = acc[mi][jn][0];
                Cs[r1 * 132 + cc + 1]       = acc[mi][jn][1];
                Cs[(r1 + 8) * 132 + cc]     = acc[mi][jn][2];
                Cs[(r1 + 8) * 132 + cc + 1] = acc[mi][jn][3];
            }
    }
    if (wid == 8) __syncthreads();     /* pair with compute warps' pre-epilogue sync */
    __syncthreads();

    /* epilogue: bias + leaky+residual, write h + hin slabs (256 threads) */
    float* Cs = (float*)smem;
    if (tid < 256) {
#pragma unroll 1
        for (int it = 0; it < 16; it++) {
            int idx = tid + it * 256;
            int row = idx >> 5;
            int c4 = (idx & 31) * 4;
            int gr = bm + row;
            if (gr < NN) {
                float x0 = Cs[row * 132 + c4 + 0] + sbias[c4 + 0];
                float x1 = Cs[row * 132 + c4 + 1] + sbias[c4 + 1];
                float x2 = Cs[row * 132 + c4 + 2] + sbias[c4 + 2];
                float x3 = Cs[row * 132 + c4 + 3] + sbias[c4 + 3];
                x0 = (x0 > 0.0f) ? 2.0f * x0 : (1.0f + NEGS) * x0;
                x1 = (x1 > 0.0f) ? 2.0f * x1 : (1.0f + NEGS) * x1;
                x2 = (x2 > 0.0f) ? 2.0f * x2 : (1.0f + NEGS) * x2;
                x3 = (x3 > 0.0f) ? 2.0f * x3 : (1.0f + NEGS) * x3;
                int col = bn * 128 + c4;
                *(float4*)(g_h + (size_t)gr * 256 + col) = make_float4(x0, x1, x2, x3);
                __nv_bfloat16 h0 = __float2bfloat16(x0), h1 = __float2bfloat16(x1);
                __nv_bfloat16 h2 = __float2bfloat16(x2), h3 = __float2bfloat16(x3);
                uint2 hu, lu;
                hu.x = (uint32_t)__bfloat16_as_ushort(h0) | ((uint32_t)__bfloat16_as_ushort(h1) << 16);
                hu.y = (uint32_t)__bfloat16_as_ushort(h2) | ((uint32_t)__bfloat16_as_ushort(h3) << 16);
                __nv_bfloat16 q0 = __float2bfloat16(x0 - __bfloat162float(h0));
                __nv_bfloat16 q1 = __float2bfloat16(x1 - __bfloat162float(h1));
                __nv_bfloat16 q2 = __float2bfloat16(x2 - __bfloat162float(h2));
                __nv_bfloat16 q3 = __float2bfloat16(x3 - __bfloat162float(h3));
                lu.x = (uint32_t)__bfloat16_as_ushort(q0) | ((uint32_t)__bfloat16_as_ushort(q1) << 16);
                lu.y = (uint32_t)__bfloat16_as_ushort(q2) | ((uint32_t)__bfloat16_as_ushort(q3) << 16);
                size_t cb = ((size_t)(gr >> 7) * 16 + (col >> 5)) * 8192;
                uint32_t off = slab_off(gr & 127, col & 31);
                *(uint2*)((char*)hin_out + cb + off) = hu;
                *(uint2*)((char*)hin_out + cb + 8 * 8192 + off) = lu;
            }
        }
    }
}

/* ---------------- GraphNorm + SoftmaxAggregation ---------------- */
__global__ void k_gn_softmax(const float* __restrict__ gw, const float* __restrict__ gb,
                             const float* __restrict__ gs, const float* __restrict__ tptr) {
    int b = blockIdx.x;
    int c = threadIdx.x;
    int start = g_gstart[b], cnt = g_gcnt[b];
    float cntf = (cnt > 0) ? (float)cnt : 1.0f;
    float t = tptr[0];

    float s = 0.0f;
    for (int i = 0; i < cnt; i++) s += g_h[(size_t)(start + i) * F2C + c];
    float ms = (s / cntf) * gs[c];

    float v = 0.0f;
    for (int i = 0; i < cnt; i++) {
        float o = g_h[(size_t)(start + i) * F2C + c] - ms;
        v += o * o;
    }
    float inv = 1.0f / sqrtf(v / cntf + EPSV);
    float w = gw[c], bias = gb[c];
    for (int i = 0; i < cnt; i++) {
        size_t idx = (size_t)(start + i) * F2C + c;
        g_h[idx] = w * (g_h[idx] - ms) * inv + bias;
    }

    float m = -FLT_MAX;
    for (int i = 0; i < cnt; i++) m = fmaxf(m, g_h[(size_t)(start + i) * F2C + c] * t);
    float se = 0.0f, sh = 0.0f;
    for (int i = 0; i < cnt; i++) {
        float hv = g_h[(size_t)(start + i) * F2C + c];
        float e = expf(hv * t - m);
        se += e;
        sh += e * hv;
    }
    g_g[b * F2C + c] = (cnt > 0) ? (sh / se) : 0.0f;
}

/* ---------------- MLP head ---------------- */
__global__ void k_mlp1(const float* __restrict__ W, const float* __restrict__ bias) {
    __shared__ float row[F2C];
    int b = blockIdx.x, j = threadIdx.x;
    row[j] = g_g[b * F2C + j];
    __syncthreads();
    float s = bias[j];
#pragma unroll 8
    for (int k = 0; k < F2C; k++) s += row[k] * W[k * F2C + j];
    g_y1[b * F2C + j] = (s > 0.0f) ? s : NEGS * s;
}

__global__ void k_mlp2(const float* __restrict__ W, const float* __restrict__ bias) {
    __shared__ float row[F2C];
    int b = blockIdx.x, j = threadIdx.x;
    row[j] = g_y1[b * F2C + j];
    row[j + 128] = g_y1[b * F2C + j + 128];
    __syncthreads();
    float s = bias[j];
#pragma unroll 8
    for (int k = 0; k < F2C; k++) s += row[k] * W[k * FF + j];
    g_y2[b * FF + j] = (s > 0.0f) ? s : NEGS * s;
}

__global__ void k_mlp3(const float* __restrict__ W, const float* __restrict__ bias,
                       float* __restrict__ out) {
    __shared__ float row[FF];
    int b = blockIdx.x, j = threadIdx.x;
    if (j < FF) row[j] = g_y2[b * FF + j];
    __syncthreads();
    float acc[8];
#pragma unroll
    for (int r = 0; r < 8; r++) {
        int idx = j + 256 * r;
        acc[r] = (idx < AA) ? bias[idx] : 0.0f;
    }
    for (int k = 0; k < FF; k++) {
        float rv = row[k];
        const float* wr = W + (size_t)k * AA;
#pragma unroll
        for (int r = 0; r < 8; r++) {
            int idx = j + 256 * r;
            if (idx < AA) acc[r] += rv * wr[idx];
        }
    }
#pragma unroll
    for (int r = 0; r < 8; r++) {
        int idx = j + 256 * r;
        if (idx < AA) out[b * AA + idx] = acc[r];
    }
}

/* ---------------- launch ---------------- */
extern "C" void kernel_launch(void* const* d_in, const int* in_sizes, int n_in,
                              void* d_out, int out_size) {
    const int*   x     = (const int*)d_in[0];
    const int*   ei    = (const int*)d_in[1];
    const int*   batch = (const int*)d_in[2];
    const float* emb   = (const float*)d_in[3];
    const float* Wl    = (const float*)d_in[4];
    const float* bl    = (const float*)d_in[5];
    const float* Wr    = (const float*)d_in[6];
    const float* gw    = (const float*)d_in[7];
    const float* gb    = (const float*)d_in[8];
    const float* gs    = (const float*)d_in[9];
    const float* t     = (const float*)d_in[10];
    const float* W1    = (const float*)d_in[11];
    const float* b1    = (const float*)d_in[12];
    const float* W2    = (const float*)d_in[13];
    const float* b2    = (const float*)d_in[14];
    const float* W3    = (const float*)d_in[15];
    const float* b3    = (const float*)d_in[16];
    float* out = (float*)d_out;

    cudaFuncSetAttribute(k_sage_mma, cudaFuncAttributeMaxDynamicSharedMemorySize, SMEMB);

    __nv_bfloat16* hinbuf[2];
    cudaGetSymbolAddress((void**)&hinbuf[0], g_hinA);
    cudaGetSymbolAddress((void**)&hinbuf[1], g_hinB);

    /* graph structure + packing */
    k_zero<<<(NN + 255) / 256, 256>>>();
    k_embed<<<(NN * F2C + 255) / 256, 256>>>(x, emb);
    k_deg<<<(EE + 255) / 256, 256>>>(ei);
    k_scan_a<<<SCANB, 256>>>();
    k_scan_b<<<1, 256>>>();
    k_scan_c<<<(NN + 1 + 255) / 256, 256>>>();
    k_prep<<<(NN + 255) / 256, 256>>>();
    k_scatter<<<(EE + 255) / 256, 256>>>(ei);
    k_sortseg<<<(NN + 255) / 256, 256>>>();
    k_gcnt<<<(NN + 255) / 256, 256>>>(batch);
    k_gscan<<<1, BB>>>();
    k_bpack<<<(LL * NSTAGE * 2 * 4096 + 255) / 256, 256>>>(Wl, Wr);

    /* 10 SAGE layers: warp-specialized pipelined tensor-core GEMM */
    dim3 ggrid(NB, 2);
    for (int l = 0; l < LL; l++) {
        k_aggregate<<<NN, 128>>>();
        k_sage_mma<<<ggrid, 288, SMEMB>>>(l, bl + l * F2C,
                                          hinbuf[l & 1], hinbuf[(l & 1) ^ 1]);
    }

    k_gn_softmax<<<BB, F2C>>>(gw, gb, gs, t);

    k_mlp1<<<BB, F2C>>>(W1, b1);
    k_mlp2<<<BB, FF>>>(W2, b2);
    k_mlp3<<<BB, 256>>>(W3, b3, out);
}